// round 1
// baseline (speedup 1.0000x reference)
#include <cuda_runtime.h>
#include <math.h>

// ---------------- problem constants ----------------
#define B_ROWS 16384
#define IN_DIM 768
#define ENC_DIM 500
#define KCLS 43
#define VDIM 1024
#define CAT_RAW 1067          // VDIM + KCLS
#define CAT_LD  1080          // padded, multiple of 8 floats (16B aligned rows)

// ---------------- scratch (static device globals: no allocation) ----------------
__device__ float g_h  [(size_t)B_ROWS * VDIM];        // relu(x@W1^T)
__device__ float g_ml [(size_t)B_ROWS * 2 * VDIM];    // mu||logvar
__device__ float g_cat[(size_t)B_ROWS * CAT_LD];      // [sampled_z | y | 0pad]
__device__ float g_Wd [(size_t)IN_DIM * CAT_LD];      // padded decoder weight
__device__ float g_klp[B_ROWS];                        // per-row KL partials
__device__ float g_ze_s[(size_t)B_ROWS * ENC_DIM];     // fallback scratch
__device__ float g_zq_s[(size_t)B_ROWS * ENC_DIM];
__device__ float g_lg_s[(size_t)B_ROWS * KCLS];
__device__ float g_kl_s[1];
__device__ int   g_mask_mode;                          // 0=bool bytes,1=int32,2=float32

// ---------------- generic TN SGEMM: C[M,N] = A[M,K] @ B[N,K]^T (+bias)(+relu) ----------------
#define BM 128
#define BN 128
#define BK 16

template<bool RELU>
__global__ __launch_bounds__(256, 2)
void sgemm_tn(const float* __restrict__ A, int lda,
              const float* __restrict__ Bm, int ldb,
              const float* __restrict__ bias,
              float* __restrict__ C, int ldc,
              int M, int N, int K)
{
    __shared__ float As[BK][BM];
    __shared__ float Bs[BK][BN];

    const int tid = threadIdx.x;
    const int m0 = blockIdx.y * BM;
    const int n0 = blockIdx.x * BN;
    const int tx = tid & 15;
    const int ty = tid >> 4;

    float acc[8][8];
#pragma unroll
    for (int i = 0; i < 8; i++)
#pragma unroll
        for (int j = 0; j < 8; j++) acc[i][j] = 0.f;

    const int lrow = tid >> 2;        // 0..63 (two halves: +0, +64)
    const int lkq  = (tid & 3) * 4;   // 0,4,8,12

    for (int k0 = 0; k0 < K; k0 += BK) {
        // ---- load A tile (transposed into As[k][m]) ----
#pragma unroll
        for (int h = 0; h < 2; h++) {
            int row = lrow + h * 64;
            int gr = m0 + row;
            int kk = k0 + lkq;
            float4 v = make_float4(0.f, 0.f, 0.f, 0.f);
            if (gr < M) {
                const float* p = A + (size_t)gr * lda + kk;
                if (kk + 3 < K) v = *reinterpret_cast<const float4*>(p);
                else {
                    if (kk + 0 < K) v.x = p[0];
                    if (kk + 1 < K) v.y = p[1];
                    if (kk + 2 < K) v.z = p[2];
                    if (kk + 3 < K) v.w = p[3];
                }
            }
            As[lkq + 0][row] = v.x;
            As[lkq + 1][row] = v.y;
            As[lkq + 2][row] = v.z;
            As[lkq + 3][row] = v.w;
        }
        // ---- load B tile ----
#pragma unroll
        for (int h = 0; h < 2; h++) {
            int row = lrow + h * 64;
            int gr = n0 + row;
            int kk = k0 + lkq;
            float4 v = make_float4(0.f, 0.f, 0.f, 0.f);
            if (gr < N) {
                const float* p = Bm + (size_t)gr * ldb + kk;
                if (kk + 3 < K) v = *reinterpret_cast<const float4*>(p);
                else {
                    if (kk + 0 < K) v.x = p[0];
                    if (kk + 1 < K) v.y = p[1];
                    if (kk + 2 < K) v.z = p[2];
                    if (kk + 3 < K) v.w = p[3];
                }
            }
            Bs[lkq + 0][row] = v.x;
            Bs[lkq + 1][row] = v.y;
            Bs[lkq + 2][row] = v.z;
            Bs[lkq + 3][row] = v.w;
        }
        __syncthreads();

#pragma unroll
        for (int k = 0; k < BK; k++) {
            float4 a0 = *reinterpret_cast<const float4*>(&As[k][ty * 4]);
            float4 a1 = *reinterpret_cast<const float4*>(&As[k][64 + ty * 4]);
            float4 b0 = *reinterpret_cast<const float4*>(&Bs[k][tx * 4]);
            float4 b1 = *reinterpret_cast<const float4*>(&Bs[k][64 + tx * 4]);
            float a[8] = {a0.x, a0.y, a0.z, a0.w, a1.x, a1.y, a1.z, a1.w};
            float b[8] = {b0.x, b0.y, b0.z, b0.w, b1.x, b1.y, b1.z, b1.w};
#pragma unroll
            for (int i = 0; i < 8; i++)
#pragma unroll
                for (int j = 0; j < 8; j++)
                    acc[i][j] = fmaf(a[i], b[j], acc[i][j]);
        }
        __syncthreads();
    }

    // ---- epilogue ----
#pragma unroll
    for (int i = 0; i < 8; i++) {
        int row = m0 + ((i < 4) ? (ty * 4 + i) : (64 + ty * 4 + i - 4));
        if (row >= M) continue;
#pragma unroll
        for (int j = 0; j < 8; j++) {
            int col = n0 + ((j < 4) ? (tx * 4 + j) : (64 + tx * 4 + j - 4));
            if (col < N) {
                float v = acc[i][j];
                if (bias) v += bias[col];
                if (RELU) v = fmaxf(v, 0.f);
                C[(size_t)row * ldc + col] = v;
            }
        }
    }
}

// ---------------- pack Wd (768 x 1067) into padded (768 x 1080) ----------------
__global__ void pack_wd_kernel(const float* __restrict__ Wd)
{
    int idx = blockIdx.x * blockDim.x + threadIdx.x;
    const int total = IN_DIM * CAT_LD;
    if (idx >= total) return;
    int r = idx / CAT_LD;
    int c = idx - r * CAT_LD;
    g_Wd[idx] = (c < CAT_RAW) ? Wd[(size_t)r * CAT_RAW + c] : 0.f;
}

// ---------------- detect known_mask dtype (bool bytes vs int32 vs float32) ----------------
__global__ void detect_mask_kernel(const unsigned int* __restrict__ w)
{
    __shared__ int s_int, s_flt;
    if (threadIdx.x == 0) { s_int = 1; s_flt = 1; }
    __syncthreads();
    int li = 1, lf = 1;
    // 4096 words = 16KB, valid under every dtype interpretation of 16384 elements
    for (int i = threadIdx.x; i < 4096; i += blockDim.x) {
        unsigned v = w[i];
        if (v > 1u) li = 0;
        if (v != 0u && v != 0x3F800000u) lf = 0;
    }
    if (!li) atomicAnd(&s_int, 0);
    if (!lf) atomicAnd(&s_flt, 0);
    __syncthreads();
    if (threadIdx.x == 0) g_mask_mode = s_int ? 1 : (s_flt ? 2 : 0);
}

// ---------------- argmax + softmax(y) + codebook gather; one warp per row ----------------
__global__ void argmax_y_kernel(const float* __restrict__ logits,
                                const void*  __restrict__ mask,
                                const int*   __restrict__ labels,
                                const float* __restrict__ codebook,
                                float* __restrict__ zq)
{
    const int b = blockIdx.x;
    const int lane = threadIdx.x;
    const float NEG_INF = __int_as_float(0xff800000u);

    const float* lr = logits + (size_t)b * KCLS;
    float v0 = (lane < KCLS) ? lr[lane] : NEG_INF;
    float v1 = (lane + 32 < KCLS) ? lr[lane + 32] : NEG_INF;

    float m; int mi;
    if (v0 >= v1) { m = v0; mi = lane; } else { m = v1; mi = lane + 32; }
#pragma unroll
    for (int off = 16; off > 0; off >>= 1) {
        float om = __shfl_xor_sync(0xffffffffu, m, off);
        int   oi = __shfl_xor_sync(0xffffffffu, mi, off);
        if (om > m || (om == m && oi < mi)) { m = om; mi = oi; }
    }

    float e0 = (lane < KCLS) ? expf(v0 - m) : 0.f;
    float e1 = (lane + 32 < KCLS) ? expf(v1 - m) : 0.f;
    float s = e0 + e1;
#pragma unroll
    for (int off = 16; off > 0; off >>= 1)
        s += __shfl_xor_sync(0xffffffffu, s, off);
    float inv = 1.0f / s;

    int mode = g_mask_mode;
    bool known;
    if (mode == 1)      known = ((const int*)mask)[b] != 0;
    else if (mode == 2) known = ((const float*)mask)[b] != 0.f;
    else                known = ((const unsigned char*)mask)[b] != 0;
    int lab = labels[b];

    float* yr = g_cat + (size_t)b * CAT_LD + VDIM;   // 56 slots (43 real + pad)
    {
        int k = lane;
        float val = (k < KCLS) ? (known ? (k == lab ? 1.f : 0.f) : e0 * inv) : 0.f;
        yr[k] = val;
        k = lane + 32;
        if (k < CAT_LD - VDIM) {
            float val2 = (k < KCLS) ? (known ? (k == lab ? 1.f : 0.f) : e1 * inv) : 0.f;
            yr[k] = val2;
        }
    }

    const float* cr = codebook + (size_t)mi * ENC_DIM;
    float* zr = zq + (size_t)b * ENC_DIM;
    for (int i = lane; i < ENC_DIM; i += 32) zr[i] = cr[i];
}

// ---------------- reparam sample + per-row KL partial ----------------
__global__ void vae_post_kernel(const float* __restrict__ eps)
{
    const int b = blockIdx.x;
    const int t = threadIdx.x;
    const float* mlr = g_ml + (size_t)b * (2 * VDIM);
    const float* er  = eps + (size_t)b * VDIM;
    float* zr = g_cat + (size_t)b * CAT_LD;

    float kl = 0.f;
    for (int i = t; i < VDIM; i += 256) {
        float mu = mlr[i];
        float lv = mlr[VDIM + i];
        float elv = expf(lv);
        kl += 0.5f * (elv + mu * mu - 1.0f - lv);
        zr[i] = fmaf(expf(0.5f * lv), er[i], mu);
    }
    __shared__ float sm[256];
    sm[t] = kl;
    __syncthreads();
    for (int st = 128; st > 0; st >>= 1) {
        if (t < st) sm[t] += sm[t + st];
        __syncthreads();
    }
    if (t == 0) g_klp[b] = sm[0];
}

// ---------------- deterministic final KL reduction ----------------
__global__ void kl_reduce_kernel(float* __restrict__ out)
{
    const int t = threadIdx.x;
    float s = 0.f;
    for (int i = t; i < B_ROWS; i += 256) s += g_klp[i];
    __shared__ float sm[256];
    sm[t] = s;
    __syncthreads();
    for (int st = 128; st > 0; st >>= 1) {
        if (t < st) sm[t] += sm[t + st];
        __syncthreads();
    }
    if (t == 0) *out = sm[0] / (float)B_ROWS;
}

// ---------------- host-side GEMM launcher ----------------
static void launch_gemm(const float* A, int lda, const float* Bm, int ldb,
                        const float* bias, float* C, int ldc,
                        int M, int N, int K, bool relu)
{
    dim3 grid((N + BN - 1) / BN, (M + BM - 1) / BM);
    if (relu) sgemm_tn<true ><<<grid, 256>>>(A, lda, Bm, ldb, bias, C, ldc, M, N, K);
    else      sgemm_tn<false><<<grid, 256>>>(A, lda, Bm, ldb, bias, C, ldc, M, N, K);
}

extern "C" void kernel_launch(void* const* d_in, const int* in_sizes, int n_in,
                              void* d_out, int out_size)
{
    const float* x        = (const float*)d_in[0];
    const void*  mask     = d_in[1];
    const int*   labels   = (const int*)d_in[2];
    const float* eps      = (const float*)d_in[3];
    const float* W_enc    = (const float*)d_in[4];
    const float* b_enc    = (const float*)d_in[5];
    const float* codebook = (const float*)d_in[6];
    const float* W1       = (const float*)d_in[7];
    const float* b1       = (const float*)d_in[8];
    const float* W2       = (const float*)d_in[9];
    const float* b2       = (const float*)d_in[10];
    const float* Wd       = (const float*)d_in[11];
    const float* bd       = (const float*)d_in[12];

    float* out = (float*)d_out;

    // scratch symbol addresses (query each call; capture-safe, non-stream API)
    float *p_h, *p_ml, *p_cat, *p_wd, *p_ze_s, *p_zq_s, *p_lg_s, *p_kl_s;
    cudaGetSymbolAddress((void**)&p_h,    g_h);
    cudaGetSymbolAddress((void**)&p_ml,   g_ml);
    cudaGetSymbolAddress((void**)&p_cat,  g_cat);
    cudaGetSymbolAddress((void**)&p_wd,   g_Wd);
    cudaGetSymbolAddress((void**)&p_ze_s, g_ze_s);
    cudaGetSymbolAddress((void**)&p_zq_s, g_zq_s);
    cudaGetSymbolAddress((void**)&p_lg_s, g_lg_s);
    cudaGetSymbolAddress((void**)&p_kl_s, g_kl_s);

    // output layout: tuple (x_tilde, z_e_x, z_q_x, logits, kl_div) flattened.
    const size_t full_elems = (size_t)B_ROWS * (IN_DIM + ENC_DIM + ENC_DIM + KCLS) + 1;
    const bool full = ((size_t)out_size >= full_elems);
    float* xt = out;
    float* ze = full ? out + (size_t)B_ROWS * IN_DIM : p_ze_s;
    float* zq = full ? ze + (size_t)B_ROWS * ENC_DIM : p_zq_s;
    float* lg = full ? zq + (size_t)B_ROWS * ENC_DIM : p_lg_s;
    float* kl = full ? lg + (size_t)B_ROWS * KCLS    : p_kl_s;

    // independent prep
    pack_wd_kernel<<<(IN_DIM * CAT_LD + 255) / 256, 256>>>(Wd);
    detect_mask_kernel<<<1, 256>>>((const unsigned int*)mask);

    // encoder
    launch_gemm(x, IN_DIM, W_enc, IN_DIM, b_enc, ze, ENC_DIM, B_ROWS, ENC_DIM, IN_DIM, false);
    // logits
    launch_gemm(ze, ENC_DIM, codebook, ENC_DIM, nullptr, lg, KCLS, B_ROWS, KCLS, ENC_DIM, false);
    // argmax / y / z_q gather (also fills g_cat cols [1024,1080))
    argmax_y_kernel<<<B_ROWS, 32>>>(lg, mask, labels, codebook, zq);
    // VAE encoder
    launch_gemm(x, IN_DIM, W1, IN_DIM, b1, p_h, VDIM, B_ROWS, VDIM, IN_DIM, true);
    launch_gemm(p_h, VDIM, W2, VDIM, b2, p_ml, 2 * VDIM, B_ROWS, 2 * VDIM, VDIM, false);
    // reparam + KL
    vae_post_kernel<<<B_ROWS, 256>>>(eps);
    kl_reduce_kernel<<<1, 256>>>(kl);
    // decoder
    launch_gemm(p_cat, CAT_LD, p_wd, CAT_LD, bd, xt, IN_DIM, B_ROWS, IN_DIM, CAT_LD, false);
}